// round 10
// baseline (speedup 1.0000x reference)
#include <cuda_runtime.h>

#define BATCH    4096
#define IN_FEAT  4096
#define NPAIRS_TOTAL 767   // 256 + 255 + 256
#define RPT 4
#define LTHREADS 128

typedef unsigned long long ull;

// ---------------- scratch (device globals; no allocation allowed) ----------------
__device__ float g_h[(size_t)BATCH * IN_FEAT];        // 64 MB intermediate h
__device__ float g_gred[(size_t)NPAIRS_TOTAL * 1024]; // per (layer,pair): G1[512] | G2[512]

// ---------------- packed f32x2 helpers ----------------
__device__ __forceinline__ ull pack2(float c) {
    ull r; asm("mov.b64 %0, {%1, %1};" : "=l"(r) : "f"(c)); return r;
}
__device__ __forceinline__ void fma2(ull& d, ull a, ull b) {
    asm("fma.rn.f32x2 %0, %1, %2, %3;" : "=l"(d) : "l"(a), "l"(b), "l"(d));
}
__device__ __forceinline__ float2 unpack2(ull v) {
    float2 f; asm("mov.b64 {%0, %1}, %2;" : "=f"(f.x), "=f"(f.y) : "l"(v)); return f;
}

// ---------------- gate reduction for one pair, 256-thread version ----------------
__device__ __forceinline__ void reduce_one_pair_256(int gb, const float* __restrict__ src,
                                                    float* __restrict__ sG)
{
    int tid = threadIdx.x;
    float acc[16];
#pragma unroll
    for (int t = 0; t < 16; t++) acc[t] = 0.f;
#pragma unroll
    for (int rc = 0; rc < 16; rc++) {
        const float* p = src + rc * 4096;
#pragma unroll
        for (int t = 0; t < 16; t++) acc[t] += p[t * 256 + tid];
    }
#pragma unroll
    for (int t = 0; t < 16; t++) sG[t * 256 + tid] = acc[t];
    __syncthreads();

    float* dst = g_gred + (size_t)gb * 1024;
#pragma unroll
    for (int u = 0; u < 2; u++) {
        int o = u * 256 + tid;          // 0..511
        float s1 = 0.f;
#pragma unroll
        for (int n = 0; n < 8; n++) s1 += sG[o * 8 + n];
        dst[o] = s1;                     // G1[ij][m]
        int ij = o >> 3, nn = o & 7;
        float s2 = 0.f;
#pragma unroll
        for (int m = 0; m < 8; m++) s2 += sG[ij * 64 + m * 8 + nn];
        dst[512 + o] = s2;               // G2[ij][n]
    }
}

// ---------------- gate reduction for one pair, 128-thread version ----------------
__device__ __forceinline__ void reduce_one_pair_128(int gb, const float* __restrict__ src,
                                                    float* __restrict__ sG)
{
    int tid = threadIdx.x;
#pragma unroll 1
    for (int half = 0; half < 2; half++) {           // keep body small
        float acc[16];
#pragma unroll
        for (int t = 0; t < 16; t++) acc[t] = 0.f;
#pragma unroll 4
        for (int rc = 0; rc < 16; rc++) {
            const float* p = src + rc * 4096 + half * 2048;
#pragma unroll
            for (int t = 0; t < 16; t++) acc[t] += p[t * 128 + tid];
        }
#pragma unroll
        for (int t = 0; t < 16; t++) sG[half * 2048 + t * 128 + tid] = acc[t];
    }
    __syncthreads();

    float* dst = g_gred + (size_t)gb * 1024;
#pragma unroll
    for (int u = 0; u < 4; u++) {
        int o = u * 128 + tid;          // 0..511
        float s1 = 0.f;
#pragma unroll
        for (int n = 0; n < 8; n++) s1 += sG[o * 8 + n];
        dst[o] = s1;                     // G1[ij][m]
        int ij = o >> 3, nn = o & 7;
        float s2 = 0.f;
#pragma unroll
        for (int m = 0; m < 8; m++) s2 += sG[ij * 64 + m * 8 + nn];
        dst[512 + o] = s2;               // G2[ij][n]
    }
}

// ---------------- Prep kernel: gates0 reduction + permuted gather ----------------
__global__ __launch_bounds__(256) void prep_kernel(
    const float* __restrict__ g0,
    const float* __restrict__ x, const int* __restrict__ perm)
{
    __shared__ float sG[4096];
    if (blockIdx.x < 256) {
        reduce_one_pair_256(blockIdx.x, g0 + (size_t)blockIdx.x * 65536, sG);
        return;
    }
    int b = blockIdx.x - 256;
    const float* xr = x + (size_t)b * IN_FEAT;
    float* hr = g_h + (size_t)b * IN_FEAT;
    int tid = threadIdx.x;
#pragma unroll
    for (int c = 0; c < 16; c++) {
        int q = c * 256 + tid;
        hr[q] = xr[perm[q]];
    }
}

// ---------------- Layer kernel: uniform-LDG gates, high occupancy ----------------
// R9 showed the binder is the L1 SHARED-MEM wavefront path: LDS.128 broadcast
// replicates 512B through the crossbar (4 wavefronts, ~8.3 LSU-cyc). An LDG
// with a warp-UNIFORM address touches ONE 128B line -> 1 wavefront (~8x
// cheaper; l1tex cost = lines touched, not lanes). So gates are read directly
// from global (__ldg, L1-resident 4KB/pair) -- no SMEM staging, no LDS for
// gates. SMEM keeps only the x1 row staging (padded stride-9, conflict-free).
// Two passes over gate halves keep accs at 4 ull/row -> ~96 regs -> 5 CTAs
// (20 warps/SM) for latency cover. fma pipe (~40us/layer aggregate demand)
// becomes the binder.
// FUSE_REDUCE: leading 511 blocks (y==0) reduce gates for layers 1-2.
template<int OFFSET, bool EPI, bool FUSE_REDUCE>
__global__ __launch_bounds__(LTHREADS, 5) void layer_kernel(
    int gate_base,
    const float* __restrict__ g1r, const float* __restrict__ g2r,
    const float* __restrict__ alphap,
    const float* __restrict__ scale,
    const float* __restrict__ bias,
    float* __restrict__ out)
{
    __shared__ float sS[4608];   // 18KB: x1 staging (512 rows x 9) / reduce area (4096)

    int kx = blockIdx.x;
    if (FUSE_REDUCE) {
        if (kx < 511) {
            if (blockIdx.y == 0) {
                int gb = 256 + kx;
                const float* src = (gb < 511) ? g1r + (size_t)(gb - 256) * 65536
                                              : g2r + (size_t)(gb - 511) * 65536;
                reduce_one_pair_128(gb, src, sS);
            }
            return;
        }
        kx -= 511;
    }
    const int k = kx;
    const int tid = threadIdx.x;
    float* sX = sS;

    const size_t col = ((size_t)(OFFSET + 2 * k)) * 8;   // 16 contiguous floats
    const int r0 = blockIdx.y * (LTHREADS * RPT) + tid;

    // load h rows: x1 -> SMEM staging, x2 -> registers
    float x2r[RPT][8];
#pragma unroll
    for (int rr = 0; rr < RPT; rr++) {
        const float4* hp = (const float4*)(g_h + (size_t)(r0 + rr * LTHREADS) * IN_FEAT + col);
        float4 a0 = hp[0], a1 = hp[1], b0 = hp[2], b1 = hp[3];
        float* xw = sX + (tid + rr * LTHREADS) * 9;
        xw[0]=a0.x; xw[1]=a0.y; xw[2]=a0.z; xw[3]=a0.w;
        xw[4]=a1.x; xw[5]=a1.y; xw[6]=a1.z; xw[7]=a1.w;
        x2r[rr][0]=b0.x; x2r[rr][1]=b0.y; x2r[rr][2]=b0.z; x2r[rr][3]=b0.w;
        x2r[rr][4]=b1.x; x2r[rr][5]=b1.y; x2r[rr][6]=b1.z; x2r[rr][7]=b1.w;
    }
    __syncthreads();

    float al = 1.f;
    if (EPI) al = __ldg(alphap);

    // gates read directly from global: warp-uniform LDG.128, L1-resident
    const ulonglong2* __restrict__ gv =
        (const ulonglong2*)(g_gred + (size_t)(gate_base + k) * 1024);

#pragma unroll 1
    for (int pass = 0; pass < 2; pass++) {
        const ulonglong2* __restrict__ gp = gv + pass * 128;  // gate half
        ull acc[RPT][4];
#pragma unroll
        for (int rr = 0; rr < RPT; rr++)
#pragma unroll
            for (int t = 0; t < 4; t++) acc[rr][t] = 0ull;

#pragma unroll 1
        for (int i = 0; i < 8; i++) {
            float x1v[RPT];
#pragma unroll
            for (int rr = 0; rr < RPT; rr++) x1v[rr] = sX[(tid + rr * LTHREADS) * 9 + i];
#pragma unroll
            for (int j = 0; j < 8; j++) {
                const int ij = i * 8 + j;
                ulonglong2 p = __ldg(gp + ij * 2);      // G[ij][0..3]
                ulonglong2 q = __ldg(gp + ij * 2 + 1);  // G[ij][4..7]
#pragma unroll
                for (int rr = 0; rr < RPT; rr++) {
                    ull cd = pack2(x1v[rr] * x2r[rr][j]);
                    fma2(acc[rr][0], cd, p.x); fma2(acc[rr][1], cd, p.y);
                    fma2(acc[rr][2], cd, q.x); fma2(acc[rr][3], cd, q.y);
                }
            }
        }

        // epilogue for this half (8 output columns at col + pass*8)
        float sc[8], bi[8];
        if (EPI) {
#pragma unroll
            for (int t = 0; t < 8; t++) {
                sc[t] = __ldg(scale + col + pass * 8 + t);
                bi[t] = __ldg(bias  + col + pass * 8 + t);
            }
        }
#pragma unroll
        for (int rr = 0; rr < RPT; rr++) {
            float y[8];
#pragma unroll
            for (int t = 0; t < 4; t++) {
                float2 f = unpack2(acc[rr][t]); y[2 * t] = f.x; y[2 * t + 1] = f.y;
            }
            size_t base = (size_t)(r0 + rr * LTHREADS) * IN_FEAT + col + pass * 8;
            if (!EPI) {
                float4* hp = (float4*)(g_h + base);
                hp[0] = make_float4(y[0], y[1], y[2], y[3]);
                hp[1] = make_float4(y[4], y[5], y[6], y[7]);
            } else {
#pragma unroll
                for (int t = 0; t < 8; t++) y[t] = al * y[t] * sc[t] + bi[t];
                float4* op = (float4*)(out + base);
                op[0] = make_float4(y[0], y[1], y[2], y[3]);
                op[1] = make_float4(y[4], y[5], y[6], y[7]);
            }
        }
    }
}

// ---------------- launch ----------------
extern "C" void kernel_launch(void* const* d_in, const int* in_sizes, int n_in,
                              void* d_out, int out_size)
{
    (void)in_sizes; (void)n_in; (void)out_size;
    const float* x     = (const float*)d_in[0];
    const float* g0    = (const float*)d_in[1];
    const float* g1    = (const float*)d_in[2];
    const float* g2    = (const float*)d_in[3];
    const float* alpha = (const float*)d_in[4];
    const float* scale = (const float*)d_in[5];
    const float* bias  = (const float*)d_in[6];
    const int*   perm  = (const int*)d_in[7];
    float* out = (float*)d_out;

    // prep: gates0 reduce (256 blocks, scheduled first) + permuted gather (4096 blocks)
    prep_kernel<<<256 + BATCH, 256>>>(g0, x, perm);
    // layer 0: 511 leading reduce blocks (gates1+gates2) + 256 pair-blocks x 8 row-groups
    layer_kernel<0, false, true ><<<dim3(511 + 256, 8), LTHREADS>>>(0,   g1, g2, nullptr, nullptr, nullptr, nullptr);
    layer_kernel<1, false, false><<<dim3(255, 8),       LTHREADS>>>(256, nullptr, nullptr, nullptr, nullptr, nullptr, nullptr);
    layer_kernel<0, true,  false><<<dim3(256, 8),       LTHREADS>>>(511, nullptr, nullptr, alpha, scale, bias, out);
}

// round 11
// speedup vs baseline: 1.3951x; 1.3951x over previous
#include <cuda_runtime.h>

#define BATCH    4096
#define IN_FEAT  4096
#define NPAIRS_TOTAL 767   // 256 + 255 + 256
#define RPT 4
#define LTHREADS 128

typedef unsigned long long ull;

// ---------------- scratch (device globals; no allocation allowed) ----------------
__device__ float g_h[(size_t)BATCH * IN_FEAT];        // 64 MB intermediate h
__device__ float g_gred[(size_t)NPAIRS_TOTAL * 1024]; // per (layer,pair): G1[512] | G2[512]

// ---------------- packed f32x2 helpers ----------------
__device__ __forceinline__ ull pack2(float c) {
    ull r; asm("mov.b64 %0, {%1, %1};" : "=l"(r) : "f"(c)); return r;
}
__device__ __forceinline__ void fma2(ull& d, ull a, ull b) {
    asm("fma.rn.f32x2 %0, %1, %2, %3;" : "=l"(d) : "l"(a), "l"(b), "l"(d));
}
__device__ __forceinline__ float2 unpack2(ull v) {
    float2 f; asm("mov.b64 {%0, %1}, %2;" : "=f"(f.x), "=f"(f.y) : "l"(v)); return f;
}

// ---------------- gate reduction for one pair, 256-thread version ----------------
__device__ __forceinline__ void reduce_one_pair_256(int gb, const float* __restrict__ src,
                                                    float* __restrict__ sG)
{
    int tid = threadIdx.x;
    float acc[16];
#pragma unroll
    for (int t = 0; t < 16; t++) acc[t] = 0.f;
#pragma unroll
    for (int rc = 0; rc < 16; rc++) {
        const float* p = src + rc * 4096;
#pragma unroll
        for (int t = 0; t < 16; t++) acc[t] += p[t * 256 + tid];
    }
#pragma unroll
    for (int t = 0; t < 16; t++) sG[t * 256 + tid] = acc[t];
    __syncthreads();

    float* dst = g_gred + (size_t)gb * 1024;
#pragma unroll
    for (int u = 0; u < 2; u++) {
        int o = u * 256 + tid;          // 0..511
        float s1 = 0.f;
#pragma unroll
        for (int n = 0; n < 8; n++) s1 += sG[o * 8 + n];
        dst[o] = s1;                     // G1[ij][m]
        int ij = o >> 3, nn = o & 7;
        float s2 = 0.f;
#pragma unroll
        for (int m = 0; m < 8; m++) s2 += sG[ij * 64 + m * 8 + nn];
        dst[512 + o] = s2;               // G2[ij][n]
    }
}

// ---------------- gate reduction for one pair, 128-thread version ----------------
__device__ __forceinline__ void reduce_one_pair_128(int gb, const float* __restrict__ src,
                                                    float* __restrict__ sG)
{
    int tid = threadIdx.x;
#pragma unroll 1
    for (int half = 0; half < 2; half++) {           // keep body small
        float acc[16];
#pragma unroll
        for (int t = 0; t < 16; t++) acc[t] = 0.f;
#pragma unroll 4
        for (int rc = 0; rc < 16; rc++) {
            const float* p = src + rc * 4096 + half * 2048;
#pragma unroll
            for (int t = 0; t < 16; t++) acc[t] += p[t * 128 + tid];
        }
#pragma unroll
        for (int t = 0; t < 16; t++) sG[half * 2048 + t * 128 + tid] = acc[t];
    }
    __syncthreads();

    float* dst = g_gred + (size_t)gb * 1024;
#pragma unroll
    for (int u = 0; u < 4; u++) {
        int o = u * 128 + tid;          // 0..511
        float s1 = 0.f;
#pragma unroll
        for (int n = 0; n < 8; n++) s1 += sG[o * 8 + n];
        dst[o] = s1;                     // G1[ij][m]
        int ij = o >> 3, nn = o & 7;
        float s2 = 0.f;
#pragma unroll
        for (int m = 0; m < 8; m++) s2 += sG[ij * 64 + m * 8 + nn];
        dst[512 + o] = s2;               // G2[ij][n]
    }
}

// ---------------- Prep kernel: gates0 reduction + permuted gather ----------------
__global__ __launch_bounds__(256) void prep_kernel(
    const float* __restrict__ g0,
    const float* __restrict__ x, const int* __restrict__ perm)
{
    __shared__ float sG[4096];
    if (blockIdx.x < 256) {
        reduce_one_pair_256(blockIdx.x, g0 + (size_t)blockIdx.x * 65536, sG);
        return;
    }
    int b = blockIdx.x - 256;
    const float* xr = x + (size_t)b * IN_FEAT;
    float* hr = g_h + (size_t)b * IN_FEAT;
    int tid = threadIdx.x;
#pragma unroll
    for (int c = 0; c < 16; c++) {
        int q = c * 256 + tid;
        hr[q] = xr[perm[q]];
    }
}

// ---------------- Layer kernel: R9 + gate double-buffer prefetch ----------------
// R9 analysis: fma demand ~70K cyc and LSU demand ~67K cyc ADD to ~128K
// measured -- gate LDS results are consumed ~2 instrs after issue, so every
// warp serializes LDS latency (29cy) with its fma work. Fix: software
// prefetch (p,q) of iteration j+1 during the fma block of j (~24 issue slots
// of distance >= LDS latency). Bounds (128,4): 128 regs so ptxas can hold the
// prefetch registers without spilling; 4 CTAs = 16 warps/SM.
// FUSE_REDUCE: leading 511 blocks (y==0) reduce gates for layers 1-2.
template<int OFFSET, bool EPI, bool FUSE_REDUCE>
__global__ __launch_bounds__(LTHREADS, 4) void layer_kernel(
    int gate_base,
    const float* __restrict__ g1r, const float* __restrict__ g2r,
    const float* __restrict__ alphap,
    const float* __restrict__ scale,
    const float* __restrict__ bias,
    float* __restrict__ out)
{
    __shared__ float sS[1024 + 512 * 9];   // 4KB gates | 18KB x1 staging (>=16KB for reduce)

    int kx = blockIdx.x;
    if (FUSE_REDUCE) {
        if (kx < 511) {
            if (blockIdx.y == 0) {
                int gb = 256 + kx;
                const float* src = (gb < 511) ? g1r + (size_t)(gb - 256) * 65536
                                              : g2r + (size_t)(gb - 511) * 65536;
                reduce_one_pair_128(gb, src, sS);
            }
            return;
        }
        kx -= 511;
    }
    const int k = kx;
    const int tid = threadIdx.x;

    // stage this pair's 1024 gate floats into SMEM (4KB)
    {
        const float4* gsrc = (const float4*)(g_gred + (size_t)(gate_base + k) * 1024);
        ((float4*)sS)[tid]       = gsrc[tid];
        ((float4*)sS)[tid + 128] = gsrc[tid + 128];
    }
    float* sX = sS + 1024;

    const size_t col = ((size_t)(OFFSET + 2 * k)) * 8;   // 16 contiguous floats
    const int r0 = blockIdx.y * (LTHREADS * RPT) + tid;

    // load h rows: x1 -> SMEM staging, x2 -> registers
    float x2r[RPT][8];
#pragma unroll
    for (int rr = 0; rr < RPT; rr++) {
        const float4* hp = (const float4*)(g_h + (size_t)(r0 + rr * LTHREADS) * IN_FEAT + col);
        float4 a0 = hp[0], a1 = hp[1], b0 = hp[2], b1 = hp[3];
        float* xw = sX + (tid + rr * LTHREADS) * 9;
        xw[0]=a0.x; xw[1]=a0.y; xw[2]=a0.z; xw[3]=a0.w;
        xw[4]=a1.x; xw[5]=a1.y; xw[6]=a1.z; xw[7]=a1.w;
        x2r[rr][0]=b0.x; x2r[rr][1]=b0.y; x2r[rr][2]=b0.z; x2r[rr][3]=b0.w;
        x2r[rr][4]=b1.x; x2r[rr][5]=b1.y; x2r[rr][6]=b1.z; x2r[rr][7]=b1.w;
    }
    __syncthreads();

    float al = 1.f;
    if (EPI) al = __ldg(alphap);

    const ulonglong2* sgv = (const ulonglong2*)sS;   // 16B = 2 packed f32x2

#pragma unroll 1
    for (int pass = 0; pass < 2; pass++) {
        const int gofs = pass * 128;          // ulonglong2 offset of gate half
        ull acc[RPT][4];
#pragma unroll
        for (int rr = 0; rr < RPT; rr++)
#pragma unroll
            for (int t = 0; t < 4; t++) acc[rr][t] = 0ull;

#pragma unroll 1
        for (int i = 0; i < 8; i++) {
            float x1v[RPT];
#pragma unroll
            for (int rr = 0; rr < RPT; rr++) x1v[rr] = sX[(tid + rr * LTHREADS) * 9 + i];

            // double-buffered gate fetch: load j+1 while computing j
            ulonglong2 p = sgv[gofs + (i * 8) * 2];
            ulonglong2 q = sgv[gofs + (i * 8) * 2 + 1];
#pragma unroll
            for (int j = 0; j < 8; j++) {
                ulonglong2 pn, qn;
                if (j < 7) {
                    pn = sgv[gofs + (i * 8 + j + 1) * 2];
                    qn = sgv[gofs + (i * 8 + j + 1) * 2 + 1];
                }
#pragma unroll
                for (int rr = 0; rr < RPT; rr++) {
                    ull cd = pack2(x1v[rr] * x2r[rr][j]);
                    fma2(acc[rr][0], cd, p.x); fma2(acc[rr][1], cd, p.y);
                    fma2(acc[rr][2], cd, q.x); fma2(acc[rr][3], cd, q.y);
                }
                if (j < 7) { p = pn; q = qn; }
            }
        }

        // epilogue for this half (8 output columns at col + pass*8)
        float sc[8], bi[8];
        if (EPI) {
#pragma unroll
            for (int t = 0; t < 8; t++) {
                sc[t] = __ldg(scale + col + pass * 8 + t);
                bi[t] = __ldg(bias  + col + pass * 8 + t);
            }
        }
#pragma unroll
        for (int rr = 0; rr < RPT; rr++) {
            float y[8];
#pragma unroll
            for (int t = 0; t < 4; t++) {
                float2 f = unpack2(acc[rr][t]); y[2 * t] = f.x; y[2 * t + 1] = f.y;
            }
            size_t base = (size_t)(r0 + rr * LTHREADS) * IN_FEAT + col + pass * 8;
            if (!EPI) {
                float4* hp = (float4*)(g_h + base);
                hp[0] = make_float4(y[0], y[1], y[2], y[3]);
                hp[1] = make_float4(y[4], y[5], y[6], y[7]);
            } else {
#pragma unroll
                for (int t = 0; t < 8; t++) y[t] = al * y[t] * sc[t] + bi[t];
                float4* op = (float4*)(out + base);
                op[0] = make_float4(y[0], y[1], y[2], y[3]);
                op[1] = make_float4(y[4], y[5], y[6], y[7]);
            }
        }
    }
}

// ---------------- launch ----------------
extern "C" void kernel_launch(void* const* d_in, const int* in_sizes, int n_in,
                              void* d_out, int out_size)
{
    (void)in_sizes; (void)n_in; (void)out_size;
    const float* x     = (const float*)d_in[0];
    const float* g0    = (const float*)d_in[1];
    const float* g1    = (const float*)d_in[2];
    const float* g2    = (const float*)d_in[3];
    const float* alpha = (const float*)d_in[4];
    const float* scale = (const float*)d_in[5];
    const float* bias  = (const float*)d_in[6];
    const int*   perm  = (const int*)d_in[7];
    float* out = (float*)d_out;

    // prep: gates0 reduce (256 blocks, scheduled first) + permuted gather (4096 blocks)
    prep_kernel<<<256 + BATCH, 256>>>(g0, x, perm);
    // layer 0: 511 leading reduce blocks (gates1+gates2) + 256 pair-blocks x 8 row-groups
    layer_kernel<0, false, true ><<<dim3(511 + 256, 8), LTHREADS>>>(0,   g1, g2, nullptr, nullptr, nullptr, nullptr);
    layer_kernel<1, false, false><<<dim3(255, 8),       LTHREADS>>>(256, nullptr, nullptr, nullptr, nullptr, nullptr, nullptr);
    layer_kernel<0, true,  false><<<dim3(256, 8),       LTHREADS>>>(511, nullptr, nullptr, alpha, scale, bias, out);
}

// round 12
// speedup vs baseline: 1.4027x; 1.0054x over previous
#include <cuda_runtime.h>

#define BATCH    4096
#define IN_FEAT  4096
#define NPAIRS_TOTAL 767   // 256 + 255 + 256
#define RPT 4
#define LTHREADS 128

typedef unsigned long long ull;

// ---------------- scratch (device globals; no allocation allowed) ----------------
__device__ float g_h[(size_t)BATCH * IN_FEAT];        // 64 MB intermediate h
__device__ float g_gred[(size_t)NPAIRS_TOTAL * 1024]; // per (layer,pair): G1[512] | G2[512]

// ---------------- packed f32x2 helpers ----------------
__device__ __forceinline__ ull pack2(float c) {
    ull r; asm("mov.b64 %0, {%1, %1};" : "=l"(r) : "f"(c)); return r;
}
__device__ __forceinline__ void fma2(ull& d, ull a, ull b) {
    asm("fma.rn.f32x2 %0, %1, %2, %3;" : "=l"(d) : "l"(a), "l"(b), "l"(d));
}
__device__ __forceinline__ float2 unpack2(ull v) {
    float2 f; asm("mov.b64 {%0, %1}, %2;" : "=f"(f.x), "=f"(f.y) : "l"(v)); return f;
}

// ---------------- gate reduction for one pair, 256-thread version ----------------
__device__ __forceinline__ void reduce_one_pair_256(int gb, const float* __restrict__ src,
                                                    float* __restrict__ sG)
{
    int tid = threadIdx.x;
    float acc[16];
#pragma unroll
    for (int t = 0; t < 16; t++) acc[t] = 0.f;
#pragma unroll
    for (int rc = 0; rc < 16; rc++) {
        const float* p = src + rc * 4096;
#pragma unroll
        for (int t = 0; t < 16; t++) acc[t] += p[t * 256 + tid];
    }
#pragma unroll
    for (int t = 0; t < 16; t++) sG[t * 256 + tid] = acc[t];
    __syncthreads();

    float* dst = g_gred + (size_t)gb * 1024;
#pragma unroll
    for (int u = 0; u < 2; u++) {
        int o = u * 256 + tid;          // 0..511
        float s1 = 0.f;
#pragma unroll
        for (int n = 0; n < 8; n++) s1 += sG[o * 8 + n];
        dst[o] = s1;                     // G1[ij][m]
        int ij = o >> 3, nn = o & 7;
        float s2 = 0.f;
#pragma unroll
        for (int m = 0; m < 8; m++) s2 += sG[ij * 64 + m * 8 + nn];
        dst[512 + o] = s2;               // G2[ij][n]
    }
}

// ---------------- gate reduction for one pair, 128-thread version ----------------
__device__ __forceinline__ void reduce_one_pair_128(int gb, const float* __restrict__ src,
                                                    float* __restrict__ sG)
{
    int tid = threadIdx.x;
#pragma unroll 1
    for (int half = 0; half < 2; half++) {           // keep body small
        float acc[16];
#pragma unroll
        for (int t = 0; t < 16; t++) acc[t] = 0.f;
#pragma unroll 4
        for (int rc = 0; rc < 16; rc++) {
            const float* p = src + rc * 4096 + half * 2048;
#pragma unroll
            for (int t = 0; t < 16; t++) acc[t] += p[t * 128 + tid];
        }
#pragma unroll
        for (int t = 0; t < 16; t++) sG[half * 2048 + t * 128 + tid] = acc[t];
    }
    __syncthreads();

    float* dst = g_gred + (size_t)gb * 1024;
#pragma unroll
    for (int u = 0; u < 4; u++) {
        int o = u * 128 + tid;          // 0..511
        float s1 = 0.f;
#pragma unroll
        for (int n = 0; n < 8; n++) s1 += sG[o * 8 + n];
        dst[o] = s1;                     // G1[ij][m]
        int ij = o >> 3, nn = o & 7;
        float s2 = 0.f;
#pragma unroll
        for (int m = 0; m < 8; m++) s2 += sG[ij * 64 + m * 8 + nn];
        dst[512 + o] = s2;               // G2[ij][n]
    }
}

// ---------------- Prep kernel: gates0 reduction + permuted gather ----------------
__global__ __launch_bounds__(256) void prep_kernel(
    const float* __restrict__ g0,
    const float* __restrict__ x, const int* __restrict__ perm)
{
    __shared__ float sG[4096];
    if (blockIdx.x < 256) {
        reduce_one_pair_256(blockIdx.x, g0 + (size_t)blockIdx.x * 65536, sG);
        return;
    }
    int b = blockIdx.x - 256;
    const float* xr = x + (size_t)b * IN_FEAT;
    float* hr = g_h + (size_t)b * IN_FEAT;
    int tid = threadIdx.x;
#pragma unroll
    for (int c = 0; c < 16; c++) {
        int q = c * 256 + tid;
        hr[q] = xr[perm[q]];
    }
}

// ---------------- Layer kernel: R9 + gate double-buffer prefetch ----------------
// R9 analysis: fma demand ~70K cyc and LSU demand ~67K cyc ADD to ~128K
// measured -- gate LDS results are consumed ~2 instrs after issue, so every
// warp serializes LDS latency (29cy) with its fma work. Fix: software
// prefetch (p,q) of iteration j+1 during the fma block of j (~24 issue slots
// of distance >= LDS latency). Bounds (128,4): 128 regs so ptxas can hold the
// prefetch registers without spilling; 4 CTAs = 16 warps/SM.
// FUSE_REDUCE: leading 511 blocks (y==0) reduce gates for layers 1-2.
template<int OFFSET, bool EPI, bool FUSE_REDUCE>
__global__ __launch_bounds__(LTHREADS, 4) void layer_kernel(
    int gate_base,
    const float* __restrict__ g1r, const float* __restrict__ g2r,
    const float* __restrict__ alphap,
    const float* __restrict__ scale,
    const float* __restrict__ bias,
    float* __restrict__ out)
{
    __shared__ float sS[1024 + 512 * 9];   // 4KB gates | 18KB x1 staging (>=16KB for reduce)

    int kx = blockIdx.x;
    if (FUSE_REDUCE) {
        if (kx < 511) {
            if (blockIdx.y == 0) {
                int gb = 256 + kx;
                const float* src = (gb < 511) ? g1r + (size_t)(gb - 256) * 65536
                                              : g2r + (size_t)(gb - 511) * 65536;
                reduce_one_pair_128(gb, src, sS);
            }
            return;
        }
        kx -= 511;
    }
    const int k = kx;
    const int tid = threadIdx.x;

    // stage this pair's 1024 gate floats into SMEM (4KB)
    {
        const float4* gsrc = (const float4*)(g_gred + (size_t)(gate_base + k) * 1024);
        ((float4*)sS)[tid]       = gsrc[tid];
        ((float4*)sS)[tid + 128] = gsrc[tid + 128];
    }
    float* sX = sS + 1024;

    const size_t col = ((size_t)(OFFSET + 2 * k)) * 8;   // 16 contiguous floats
    const int r0 = blockIdx.y * (LTHREADS * RPT) + tid;

    // load h rows: x1 -> SMEM staging, x2 -> registers
    float x2r[RPT][8];
#pragma unroll
    for (int rr = 0; rr < RPT; rr++) {
        const float4* hp = (const float4*)(g_h + (size_t)(r0 + rr * LTHREADS) * IN_FEAT + col);
        float4 a0 = hp[0], a1 = hp[1], b0 = hp[2], b1 = hp[3];
        float* xw = sX + (tid + rr * LTHREADS) * 9;
        xw[0]=a0.x; xw[1]=a0.y; xw[2]=a0.z; xw[3]=a0.w;
        xw[4]=a1.x; xw[5]=a1.y; xw[6]=a1.z; xw[7]=a1.w;
        x2r[rr][0]=b0.x; x2r[rr][1]=b0.y; x2r[rr][2]=b0.z; x2r[rr][3]=b0.w;
        x2r[rr][4]=b1.x; x2r[rr][5]=b1.y; x2r[rr][6]=b1.z; x2r[rr][7]=b1.w;
    }
    __syncthreads();

    float al = 1.f;
    if (EPI) al = __ldg(alphap);

    const ulonglong2* sgv = (const ulonglong2*)sS;   // 16B = 2 packed f32x2

#pragma unroll 1
    for (int pass = 0; pass < 2; pass++) {
        const int gofs = pass * 128;          // ulonglong2 offset of gate half
        ull acc[RPT][4];
#pragma unroll
        for (int rr = 0; rr < RPT; rr++)
#pragma unroll
            for (int t = 0; t < 4; t++) acc[rr][t] = 0ull;

#pragma unroll 1
        for (int i = 0; i < 8; i++) {
            float x1v[RPT];
#pragma unroll
            for (int rr = 0; rr < RPT; rr++) x1v[rr] = sX[(tid + rr * LTHREADS) * 9 + i];

            // double-buffered gate fetch: load j+1 while computing j
            ulonglong2 p = sgv[gofs + (i * 8) * 2];
            ulonglong2 q = sgv[gofs + (i * 8) * 2 + 1];
#pragma unroll
            for (int j = 0; j < 8; j++) {
                ulonglong2 pn, qn;
                if (j < 7) {
                    pn = sgv[gofs + (i * 8 + j + 1) * 2];
                    qn = sgv[gofs + (i * 8 + j + 1) * 2 + 1];
                }
#pragma unroll
                for (int rr = 0; rr < RPT; rr++) {
                    ull cd = pack2(x1v[rr] * x2r[rr][j]);
                    fma2(acc[rr][0], cd, p.x); fma2(acc[rr][1], cd, p.y);
                    fma2(acc[rr][2], cd, q.x); fma2(acc[rr][3], cd, q.y);
                }
                if (j < 7) { p = pn; q = qn; }
            }
        }

        // epilogue for this half (8 output columns at col + pass*8)
        float sc[8], bi[8];
        if (EPI) {
#pragma unroll
            for (int t = 0; t < 8; t++) {
                sc[t] = __ldg(scale + col + pass * 8 + t);
                bi[t] = __ldg(bias  + col + pass * 8 + t);
            }
        }
#pragma unroll
        for (int rr = 0; rr < RPT; rr++) {
            float y[8];
#pragma unroll
            for (int t = 0; t < 4; t++) {
                float2 f = unpack2(acc[rr][t]); y[2 * t] = f.x; y[2 * t + 1] = f.y;
            }
            size_t base = (size_t)(r0 + rr * LTHREADS) * IN_FEAT + col + pass * 8;
            if (!EPI) {
                float4* hp = (float4*)(g_h + base);
                hp[0] = make_float4(y[0], y[1], y[2], y[3]);
                hp[1] = make_float4(y[4], y[5], y[6], y[7]);
            } else {
#pragma unroll
                for (int t = 0; t < 8; t++) y[t] = al * y[t] * sc[t] + bi[t];
                float4* op = (float4*)(out + base);
                op[0] = make_float4(y[0], y[1], y[2], y[3]);
                op[1] = make_float4(y[4], y[5], y[6], y[7]);
            }
        }
    }
}

// ---------------- launch ----------------
extern "C" void kernel_launch(void* const* d_in, const int* in_sizes, int n_in,
                              void* d_out, int out_size)
{
    (void)in_sizes; (void)n_in; (void)out_size;
    const float* x     = (const float*)d_in[0];
    const float* g0    = (const float*)d_in[1];
    const float* g1    = (const float*)d_in[2];
    const float* g2    = (const float*)d_in[3];
    const float* alpha = (const float*)d_in[4];
    const float* scale = (const float*)d_in[5];
    const float* bias  = (const float*)d_in[6];
    const int*   perm  = (const int*)d_in[7];
    float* out = (float*)d_out;

    // prep: gates0 reduce (256 blocks, scheduled first) + permuted gather (4096 blocks)
    prep_kernel<<<256 + BATCH, 256>>>(g0, x, perm);
    // layer 0: 511 leading reduce blocks (gates1+gates2) + 256 pair-blocks x 8 row-groups
    layer_kernel<0, false, true ><<<dim3(511 + 256, 8), LTHREADS>>>(0,   g1, g2, nullptr, nullptr, nullptr, nullptr);
    layer_kernel<1, false, false><<<dim3(255, 8),       LTHREADS>>>(256, nullptr, nullptr, nullptr, nullptr, nullptr, nullptr);
    layer_kernel<0, true,  false><<<dim3(256, 8),       LTHREADS>>>(511, nullptr, nullptr, alpha, scale, bias, out);
}

// round 13
// speedup vs baseline: 1.6331x; 1.1643x over previous
#include <cuda_runtime.h>
#include <cstdint>

#define BATCH    4096
#define IN_FEAT  4096
#define NPAIRS_TOTAL 767   // 256 + 255 + 256
#define GT_STRIDE 68       // padded [16][68] gate tiles (bank-conflict-free)
#define GT_PAIR   (16 * GT_STRIDE)

// ---------------- scratch (device globals; no allocation allowed) ----------------
__device__ float g_h[(size_t)BATCH * IN_FEAT];              // 64 MB intermediate h
__device__ float g_gthi[(size_t)NPAIRS_TOTAL * GT_PAIR];    // gates^T hi (tf32-exact)
__device__ float g_gtlo[(size_t)NPAIRS_TOTAL * GT_PAIR];    // gates^T lo residual

// ---------------- tf32 helpers ----------------
__device__ __forceinline__ uint32_t tf32_hi(float x) {
    uint32_t h; asm("cvt.rna.tf32.f32 %0, %1;" : "=r"(h) : "f"(x)); return h;
}
// D += A(tf32) * B(tf32), m16n8k8, A row-major, B col-major
__device__ __forceinline__ void mma8(float* d, const uint32_t* a, const uint32_t* b) {
    asm volatile(
        "mma.sync.aligned.m16n8k8.row.col.f32.tf32.tf32.f32 "
        "{%0,%1,%2,%3}, {%4,%5,%6,%7}, {%8,%9}, {%0,%1,%2,%3};"
        : "+f"(d[0]), "+f"(d[1]), "+f"(d[2]), "+f"(d[3])
        : "r"(a[0]), "r"(a[1]), "r"(a[2]), "r"(a[3]), "r"(b[0]), "r"(b[1]));
}

// ---------------- gate reduction: emit transposed hi/lo tiles ----------------
// gT[m][ij] for m=0..7 from G1, gT[8+n][ij] from G2.
__device__ __forceinline__ void store_gt(int gb, int o, float s1, float s2) {
    float* dh = g_gthi + (size_t)gb * GT_PAIR;
    float* dl = g_gtlo + (size_t)gb * GT_PAIR;
    int ij = o >> 3, m = o & 7;
    float h1 = __uint_as_float(tf32_hi(s1));
    dh[m * GT_STRIDE + ij] = h1;  dl[m * GT_STRIDE + ij] = s1 - h1;
    float h2 = __uint_as_float(tf32_hi(s2));
    dh[(8 + m) * GT_STRIDE + ij] = h2;  dl[(8 + m) * GT_STRIDE + ij] = s2 - h2;
}

__device__ __forceinline__ void reduce_one_pair_256(int gb, const float* __restrict__ src,
                                                    float* __restrict__ sG)
{
    int tid = threadIdx.x;
    float acc[16];
#pragma unroll
    for (int t = 0; t < 16; t++) acc[t] = 0.f;
#pragma unroll
    for (int rc = 0; rc < 16; rc++) {
        const float* p = src + rc * 4096;
#pragma unroll
        for (int t = 0; t < 16; t++) acc[t] += p[t * 256 + tid];
    }
#pragma unroll
    for (int t = 0; t < 16; t++) sG[t * 256 + tid] = acc[t];
    __syncthreads();
#pragma unroll
    for (int u = 0; u < 2; u++) {
        int o = u * 256 + tid;          // 0..511
        float s1 = 0.f;
#pragma unroll
        for (int n = 0; n < 8; n++) s1 += sG[o * 8 + n];
        int ij = o >> 3, nn = o & 7;
        float s2 = 0.f;
#pragma unroll
        for (int m = 0; m < 8; m++) s2 += sG[ij * 64 + m * 8 + nn];
        store_gt(gb, o, s1, s2);
    }
}

__device__ __forceinline__ void reduce_one_pair_128(int gb, const float* __restrict__ src,
                                                    float* __restrict__ sG)
{
    int tid = threadIdx.x;
#pragma unroll 1
    for (int half = 0; half < 2; half++) {
        float acc[16];
#pragma unroll
        for (int t = 0; t < 16; t++) acc[t] = 0.f;
#pragma unroll 4
        for (int rc = 0; rc < 16; rc++) {
            const float* p = src + rc * 4096 + half * 2048;
#pragma unroll
            for (int t = 0; t < 16; t++) acc[t] += p[t * 128 + tid];
        }
#pragma unroll
        for (int t = 0; t < 16; t++) sG[half * 2048 + t * 128 + tid] = acc[t];
    }
    __syncthreads();
#pragma unroll
    for (int u = 0; u < 4; u++) {
        int o = u * 128 + tid;          // 0..511
        float s1 = 0.f;
#pragma unroll
        for (int n = 0; n < 8; n++) s1 += sG[o * 8 + n];
        int ij = o >> 3, nn = o & 7;
        float s2 = 0.f;
#pragma unroll
        for (int m = 0; m < 8; m++) s2 += sG[ij * 64 + m * 8 + nn];
        store_gt(gb, o, s1, s2);
    }
}

// ---------------- Prep kernel: gates0 reduction + permuted gather ----------------
__global__ __launch_bounds__(256) void prep_kernel(
    const float* __restrict__ g0,
    const float* __restrict__ x, const int* __restrict__ perm)
{
    __shared__ float sG[4096];
    if (blockIdx.x < 256) {
        reduce_one_pair_256(blockIdx.x, g0 + (size_t)blockIdx.x * 65536, sG);
        return;
    }
    int b = blockIdx.x - 256;
    const float* xr = x + (size_t)b * IN_FEAT;
    float* hr = g_h + (size_t)b * IN_FEAT;
    int tid = threadIdx.x;
#pragma unroll
    for (int c = 0; c < 16; c++) {
        int q = c * 256 + tid;
        hr[q] = xr[perm[q]];
    }
}

// ---------------- Layer kernel: per-pair GEMM on tensor cores ----------------
// Y[4096 x 16] = O[4096 x 64] * G[64 x 16] per pair, via mma.sync m16n8k8 tf32
// with 3-term split precision (hi*hi + hi*lo + lo*hi ~ fp32 accuracy).
// Key identity: k-chunk kc <-> i=kc, in-chunk col <-> j, so A-fragments are
// a = x1[row][kc] * x2[row][j] built IN REGISTERS: no O materialization, no
// SMEM crossbar traffic at all in the mainloop. Gate B-fragments (transposed,
// pre-split in the reduce) are loaded once per block-job into 64 registers.
// Warp = 16 rows x 16 outputs per mma-group; 4 warps x 4 tile-iters = 256
// rows per block. FUSE_REDUCE: leading 511 x-blocks (y==0) reduce layers 1-2
// gates, overlapping with layer-0 tensor work.
template<int OFFSET, bool EPI, bool FUSE_REDUCE>
__global__ __launch_bounds__(128, 3) void layer_kernel(
    int gate_base,
    const float* __restrict__ g1r, const float* __restrict__ g2r,
    const float* __restrict__ alphap,
    const float* __restrict__ scale,
    const float* __restrict__ bias,
    float* __restrict__ out)
{
    __shared__ float sS[4096];

    int kx = blockIdx.x;
    if (FUSE_REDUCE) {
        if (kx < 511) {
            if (blockIdx.y == 0) {
                int gb = 256 + kx;
                const float* src = (gb < 511) ? g1r + (size_t)(gb - 256) * 65536
                                              : g2r + (size_t)(gb - 511) * 65536;
                reduce_one_pair_128(gb, src, sS);
            }
            return;
        }
        kx -= 511;
    }
    const int k = kx;
    const int tid = threadIdx.x;
    const int w = tid >> 5, t = tid & 31;
    const int g = t >> 2, tg = t & 3;
    const size_t col = ((size_t)(OFFSET + 2 * k)) * 8;   // 16 contiguous h columns

    // ---- B fragments for this pair: held in registers for the whole job ----
    const float* bh = g_gthi + (size_t)(gate_base + k) * GT_PAIR;
    const float* bl = g_gtlo + (size_t)(gate_base + k) * GT_PAIR;
    uint32_t bhi[2][8][2], blo[2][8][2];
#pragma unroll
    for (int nb = 0; nb < 2; nb++)
#pragma unroll
        for (int kc = 0; kc < 8; kc++) {
            int idx = (nb * 8 + g) * GT_STRIDE + kc * 8 + tg;
            bhi[nb][kc][0] = __float_as_uint(__ldg(bh + idx));
            bhi[nb][kc][1] = __float_as_uint(__ldg(bh + idx + 4));
            blo[nb][kc][0] = __float_as_uint(__ldg(bl + idx));
            blo[nb][kc][1] = __float_as_uint(__ldg(bl + idx + 4));
        }

    float al = 1.f;
    float sc[2][2], bi[2][2];
    if (EPI) {
        al = __ldg(alphap);
#pragma unroll
        for (int nb = 0; nb < 2; nb++)
#pragma unroll
            for (int e = 0; e < 2; e++) {
                size_t c = col + nb * 8 + 2 * tg + e;
                sc[nb][e] = __ldg(scale + c);
                bi[nb][e] = __ldg(bias + c);
            }
    }

#pragma unroll 1
    for (int it = 0; it < 4; it++) {
        int rbase = blockIdx.y * 256 + it * 64 + w * 16;
        int ra = rbase + g, rb = rbase + g + 8;
        const float* pa = g_h + (size_t)ra * IN_FEAT + col;
        const float* pb = g_h + (size_t)rb * IN_FEAT + col;
        float4 a0 = *(const float4*)pa, a1 = *(const float4*)(pa + 4);
        float4 c0 = *(const float4*)pb, c1 = *(const float4*)(pb + 4);
        float x1a[8] = {a0.x, a0.y, a0.z, a0.w, a1.x, a1.y, a1.z, a1.w};
        float x1b[8] = {c0.x, c0.y, c0.z, c0.w, c1.x, c1.y, c1.z, c1.w};
        float x2a0 = __ldg(pa + 8 + tg), x2a1 = __ldg(pa + 12 + tg);
        float x2b0 = __ldg(pb + 8 + tg), x2b1 = __ldg(pb + 12 + tg);

        float d0[4] = {0.f, 0.f, 0.f, 0.f};
        float d1[4] = {0.f, 0.f, 0.f, 0.f};

#pragma unroll
        for (int kc = 0; kc < 8; kc++) {
            // A fragment (row-major m16k8): a0:(g,tg) a1:(g+8,tg) a2:(g,tg+4) a3:(g+8,tg+4)
            float av[4] = { x1a[kc] * x2a0, x1b[kc] * x2b0,
                            x1a[kc] * x2a1, x1b[kc] * x2b1 };
            uint32_t ah[4], alo_[4];
#pragma unroll
            for (int e = 0; e < 4; e++) {
                ah[e] = tf32_hi(av[e]);
                alo_[e] = __float_as_uint(av[e] - __uint_as_float(ah[e]));
            }
            mma8(d0, ah,   bhi[0][kc]);
            mma8(d0, ah,   blo[0][kc]);
            mma8(d0, alo_, bhi[0][kc]);
            mma8(d1, ah,   bhi[1][kc]);
            mma8(d1, ah,   blo[1][kc]);
            mma8(d1, alo_, bhi[1][kc]);
        }

        // D fragment: d0,d1 = row g cols 2tg,2tg+1 ; d2,d3 = row g+8 same cols
#pragma unroll
        for (int nb = 0; nb < 2; nb++) {
            float* d = nb ? d1 : d0;
            size_t ca = (size_t)ra * IN_FEAT + col + nb * 8 + 2 * tg;
            size_t cb = (size_t)rb * IN_FEAT + col + nb * 8 + 2 * tg;
            if (!EPI) {
                *(float2*)(g_h + ca) = make_float2(d[0], d[1]);
                *(float2*)(g_h + cb) = make_float2(d[2], d[3]);
            } else {
                *(float2*)(out + ca) = make_float2(al * d[0] * sc[nb][0] + bi[nb][0],
                                                   al * d[1] * sc[nb][1] + bi[nb][1]);
                *(float2*)(out + cb) = make_float2(al * d[2] * sc[nb][0] + bi[nb][0],
                                                   al * d[3] * sc[nb][1] + bi[nb][1]);
            }
        }
    }
}

// ---------------- launch ----------------
extern "C" void kernel_launch(void* const* d_in, const int* in_sizes, int n_in,
                              void* d_out, int out_size)
{
    (void)in_sizes; (void)n_in; (void)out_size;
    const float* x     = (const float*)d_in[0];
    const float* g0    = (const float*)d_in[1];
    const float* g1    = (const float*)d_in[2];
    const float* g2    = (const float*)d_in[3];
    const float* alpha = (const float*)d_in[4];
    const float* scale = (const float*)d_in[5];
    const float* bias  = (const float*)d_in[6];
    const int*   perm  = (const int*)d_in[7];
    float* out = (float*)d_out;

    // prep: gates0 reduce (256 blocks) + permuted gather (4096 blocks)
    prep_kernel<<<256 + BATCH, 256>>>(g0, x, perm);
    // layer 0: 511 leading reduce blocks (gates1+gates2) + 256 pair-blocks x 16 row-groups
    layer_kernel<0, false, true ><<<dim3(511 + 256, 16), 128>>>(0,   g1, g2, nullptr, nullptr, nullptr, nullptr);
    layer_kernel<1, false, false><<<dim3(255, 16),       128>>>(256, nullptr, nullptr, nullptr, nullptr, nullptr, nullptr);
    layer_kernel<0, true,  false><<<dim3(256, 16),       128>>>(511, nullptr, nullptr, alpha, scale, bias, out);
}

// round 14
// speedup vs baseline: 1.6430x; 1.0061x over previous
#include <cuda_runtime.h>
#include <cstdint>

#define BATCH    4096
#define IN_FEAT  4096
#define NPAIRS_TOTAL 767   // 256 + 255 + 256
#define GT_STRIDE 68       // padded [16][68] gate tiles (bank-conflict-free)
#define GT_PAIR   (16 * GT_STRIDE)

// ---------------- scratch (device globals; no allocation allowed) ----------------
__device__ float g_h[(size_t)BATCH * IN_FEAT];              // 64 MB intermediate h
__device__ float g_gthi[(size_t)NPAIRS_TOTAL * GT_PAIR];    // gates^T hi (tf32-exact)
__device__ float g_gtlo[(size_t)NPAIRS_TOTAL * GT_PAIR];    // gates^T lo residual

// ---------------- tf32 helpers ----------------
__device__ __forceinline__ uint32_t tf32_hi(float x) {
    uint32_t h; asm("cvt.rna.tf32.f32 %0, %1;" : "=r"(h) : "f"(x)); return h;
}
// D += A(tf32) * B(tf32), m16n8k8, A row-major, B col-major
__device__ __forceinline__ void mma8(float* d, const uint32_t* a, const uint32_t* b) {
    asm volatile(
        "mma.sync.aligned.m16n8k8.row.col.f32.tf32.tf32.f32 "
        "{%0,%1,%2,%3}, {%4,%5,%6,%7}, {%8,%9}, {%0,%1,%2,%3};"
        : "+f"(d[0]), "+f"(d[1]), "+f"(d[2]), "+f"(d[3])
        : "r"(a[0]), "r"(a[1]), "r"(a[2]), "r"(a[3]), "r"(b[0]), "r"(b[1]));
}

// ---------------- gate reduction: emit transposed hi/lo tiles ----------------
__device__ __forceinline__ void store_gt(int gb, int o, float s1, float s2) {
    float* dh = g_gthi + (size_t)gb * GT_PAIR;
    float* dl = g_gtlo + (size_t)gb * GT_PAIR;
    int ij = o >> 3, m = o & 7;
    float h1 = __uint_as_float(tf32_hi(s1));
    dh[m * GT_STRIDE + ij] = h1;  dl[m * GT_STRIDE + ij] = s1 - h1;
    float h2 = __uint_as_float(tf32_hi(s2));
    dh[(8 + m) * GT_STRIDE + ij] = h2;  dl[(8 + m) * GT_STRIDE + ij] = s2 - h2;
}

__device__ __forceinline__ void reduce_one_pair_256(int gb, const float* __restrict__ src,
                                                    float* __restrict__ sG)
{
    int tid = threadIdx.x;
    float acc[16];
#pragma unroll
    for (int t = 0; t < 16; t++) acc[t] = 0.f;
#pragma unroll
    for (int rc = 0; rc < 16; rc++) {
        const float* p = src + rc * 4096;
#pragma unroll
        for (int t = 0; t < 16; t++) acc[t] += p[t * 256 + tid];
    }
#pragma unroll
    for (int t = 0; t < 16; t++) sG[t * 256 + tid] = acc[t];
    __syncthreads();
#pragma unroll
    for (int u = 0; u < 2; u++) {
        int o = u * 256 + tid;          // 0..511
        float s1 = 0.f;
#pragma unroll
        for (int n = 0; n < 8; n++) s1 += sG[o * 8 + n];
        int ij = o >> 3, nn = o & 7;
        float s2 = 0.f;
#pragma unroll
        for (int m = 0; m < 8; m++) s2 += sG[ij * 64 + m * 8 + nn];
        store_gt(gb, o, s1, s2);
    }
}

__device__ __forceinline__ void reduce_one_pair_128(int gb, const float* __restrict__ src,
                                                    float* __restrict__ sG)
{
    int tid = threadIdx.x;
#pragma unroll 1
    for (int half = 0; half < 2; half++) {
        float acc[16];
#pragma unroll
        for (int t = 0; t < 16; t++) acc[t] = 0.f;
#pragma unroll 4
        for (int rc = 0; rc < 16; rc++) {
            const float* p = src + rc * 4096 + half * 2048;
#pragma unroll
            for (int t = 0; t < 16; t++) acc[t] += p[t * 128 + tid];
        }
#pragma unroll
        for (int t = 0; t < 16; t++) sG[half * 2048 + t * 128 + tid] = acc[t];
    }
    __syncthreads();
#pragma unroll
    for (int u = 0; u < 4; u++) {
        int o = u * 128 + tid;          // 0..511
        float s1 = 0.f;
#pragma unroll
        for (int n = 0; n < 8; n++) s1 += sG[o * 8 + n];
        int ij = o >> 3, nn = o & 7;
        float s2 = 0.f;
#pragma unroll
        for (int m = 0; m < 8; m++) s2 += sG[ij * 64 + m * 8 + nn];
        store_gt(gb, o, s1, s2);
    }
}

// ---------------- Prep kernel: gates0 reduction + permuted gather ----------------
__global__ __launch_bounds__(256) void prep_kernel(
    const float* __restrict__ g0,
    const float* __restrict__ x, const int* __restrict__ perm)
{
    __shared__ float sG[4096];
    if (blockIdx.x < 256) {
        reduce_one_pair_256(blockIdx.x, g0 + (size_t)blockIdx.x * 65536, sG);
        return;
    }
    int b = blockIdx.x - 256;
    const float* xr = x + (size_t)b * IN_FEAT;
    float* hr = g_h + (size_t)b * IN_FEAT;
    int tid = threadIdx.x;
#pragma unroll
    for (int c = 0; c < 16; c++) {
        int q = c * 256 + tid;
        hr[q] = xr[perm[q]];
    }
}

// ---------------- Layer kernel: per-pair GEMM on tensor cores ----------------
// R13 binder: fragment loads were 4-lane-redundant LDG (8 strided rows per
// instr = 8 wavefronts; 64 wavefronts/iter vs 48 HMMA). Fix: stage each
// warp's 16x16 h tile via 2 COALESCED LDG.128 (lane->row t>>2, quarter t&3;
// 16 wavefronts), STS to pad-20 SMEM, then fragment reads are cheap LDS
// (x1: 2x LDS.128 broadcast; x2: LDS.32 at g*20+8+tg -- distinct banks
// mod 32, conflict-free). Warp-private region, __syncwarp only.
// Math identical to R13 (validated): 3-term tf32 split mma m16n8k8.
template<int OFFSET, bool EPI, bool FUSE_REDUCE>
__global__ __launch_bounds__(128, 4) void layer_kernel(
    int gate_base,
    const float* __restrict__ g1r, const float* __restrict__ g2r,
    const float* __restrict__ alphap,
    const float* __restrict__ scale,
    const float* __restrict__ bias,
    float* __restrict__ out)
{
    __shared__ float sS[4096];   // 16KB: reduce area / 4 x 320-float warp tiles

    int kx = blockIdx.x;
    if (FUSE_REDUCE) {
        if (kx < 511) {
            if (blockIdx.y == 0) {
                int gb = 256 + kx;
                const float* src = (gb < 511) ? g1r + (size_t)(gb - 256) * 65536
                                              : g2r + (size_t)(gb - 511) * 65536;
                reduce_one_pair_128(gb, src, sS);
            }
            return;
        }
        kx -= 511;
    }
    const int k = kx;
    const int tid = threadIdx.x;
    const int w = tid >> 5, t = tid & 31;
    const int g = t >> 2, tg = t & 3;
    const size_t col = ((size_t)(OFFSET + 2 * k)) * 8;   // 16 contiguous h columns
    float* sW = sS + w * 320;                            // warp-private 16x20 tile

    // ---- B fragments for this pair: held in registers for the whole job ----
    const float* bh = g_gthi + (size_t)(gate_base + k) * GT_PAIR;
    const float* bl = g_gtlo + (size_t)(gate_base + k) * GT_PAIR;
    uint32_t bhi[2][8][2], blo[2][8][2];
#pragma unroll
    for (int nb = 0; nb < 2; nb++)
#pragma unroll
        for (int kc = 0; kc < 8; kc++) {
            int idx = (nb * 8 + g) * GT_STRIDE + kc * 8 + tg;
            bhi[nb][kc][0] = __float_as_uint(__ldg(bh + idx));
            bhi[nb][kc][1] = __float_as_uint(__ldg(bh + idx + 4));
            blo[nb][kc][0] = __float_as_uint(__ldg(bl + idx));
            blo[nb][kc][1] = __float_as_uint(__ldg(bl + idx + 4));
        }

    float al = 1.f;
    float sc[2][2], bi[2][2];
    if (EPI) {
        al = __ldg(alphap);
#pragma unroll
        for (int nb = 0; nb < 2; nb++)
#pragma unroll
            for (int e = 0; e < 2; e++) {
                size_t c = col + nb * 8 + 2 * tg + e;
                sc[nb][e] = __ldg(scale + c);
                bi[nb][e] = __ldg(bias + c);
            }
    }

#pragma unroll 1
    for (int it = 0; it < 4; it++) {
        int rbase = blockIdx.y * 256 + it * 64 + w * 16;

        // ---- coalesced stage: 16 rows x 16 floats -> SMEM (pad 20) ----
#pragma unroll
        for (int hh = 0; hh < 2; hh++) {
            int row = (t >> 2) + hh * 8;
            float4 v = *(const float4*)(g_h + (size_t)(rbase + row) * IN_FEAT + col + (t & 3) * 4);
            *(float4*)(sW + row * 20 + (t & 3) * 4) = v;
        }
        __syncwarp();

        // ---- fragment reads from SMEM ----
        float4 u0 = *(const float4*)(sW + g * 20);
        float4 u1 = *(const float4*)(sW + g * 20 + 4);
        float4 v0 = *(const float4*)(sW + (g + 8) * 20);
        float4 v1 = *(const float4*)(sW + (g + 8) * 20 + 4);
        float x1a[8] = {u0.x, u0.y, u0.z, u0.w, u1.x, u1.y, u1.z, u1.w};
        float x1b[8] = {v0.x, v0.y, v0.z, v0.w, v1.x, v1.y, v1.z, v1.w};
        float x2a0 = sW[g * 20 + 8 + tg],        x2a1 = sW[g * 20 + 12 + tg];
        float x2b0 = sW[(g + 8) * 20 + 8 + tg],  x2b1 = sW[(g + 8) * 20 + 12 + tg];
        __syncwarp();   // reads done before next iter overwrites sW

        float d0[4] = {0.f, 0.f, 0.f, 0.f};
        float d1[4] = {0.f, 0.f, 0.f, 0.f};

#pragma unroll
        for (int kc = 0; kc < 8; kc++) {
            // A fragment (row-major m16k8): a0:(g,tg) a1:(g+8,tg) a2:(g,tg+4) a3:(g+8,tg+4)
            float av[4] = { x1a[kc] * x2a0, x1b[kc] * x2b0,
                            x1a[kc] * x2a1, x1b[kc] * x2b1 };
            uint32_t ah[4], alo_[4];
#pragma unroll
            for (int e = 0; e < 4; e++) {
                ah[e] = tf32_hi(av[e]);
                alo_[e] = __float_as_uint(av[e] - __uint_as_float(ah[e]));
            }
            mma8(d0, ah,   bhi[0][kc]);
            mma8(d0, ah,   blo[0][kc]);
            mma8(d0, alo_, bhi[0][kc]);
            mma8(d1, ah,   bhi[1][kc]);
            mma8(d1, ah,   blo[1][kc]);
            mma8(d1, alo_, bhi[1][kc]);
        }

        // D fragment: d0,d1 = row g cols 2tg,2tg+1 ; d2,d3 = row g+8 same cols
        int ra = rbase + g, rb = rbase + g + 8;
#pragma unroll
        for (int nb = 0; nb < 2; nb++) {
            float* d = nb ? d1 : d0;
            size_t ca = (size_t)ra * IN_FEAT + col + nb * 8 + 2 * tg;
            size_t cb = (size_t)rb * IN_FEAT + col + nb * 8 + 2 * tg;
            if (!EPI) {
                *(float2*)(g_h + ca) = make_float2(d[0], d[1]);
                *(float2*)(g_h + cb) = make_float2(d[2], d[3]);
            } else {
                *(float2*)(out + ca) = make_float2(al * d[0] * sc[nb][0] + bi[nb][0],
                                                   al * d[1] * sc[nb][1] + bi[nb][1]);
                *(float2*)(out + cb) = make_float2(al * d[2] * sc[nb][0] + bi[nb][0],
                                                   al * d[3] * sc[nb][1] + bi[nb][1]);
            }
        }
    }
}

// ---------------- launch ----------------
extern "C" void kernel_launch(void* const* d_in, const int* in_sizes, int n_in,
                              void* d_out, int out_size)
{
    (void)in_sizes; (void)n_in; (void)out_size;
    const float* x     = (const float*)d_in[0];
    const float* g0    = (const float*)d_in[1];
    const float* g1    = (const float*)d_in[2];
    const float* g2    = (const float*)d_in[3];
    const float* alpha = (const float*)d_in[4];
    const float* scale = (const float*)d_in[5];
    const float* bias  = (const float*)d_in[6];
    const int*   perm  = (const int*)d_in[7];
    float* out = (float*)d_out;

    // prep: gates0 reduce (256 blocks) + permuted gather (4096 blocks)
    prep_kernel<<<256 + BATCH, 256>>>(g0, x, perm);
    // layer 0: 511 leading reduce blocks (gates1+gates2) + 256 pair-blocks x 16 row-groups
    layer_kernel<0, false, true ><<<dim3(511 + 256, 16), 128>>>(0,   g1, g2, nullptr, nullptr, nullptr, nullptr);
    layer_kernel<1, false, false><<<dim3(255, 16),       128>>>(256, nullptr, nullptr, nullptr, nullptr, nullptr, nullptr);
    layer_kernel<0, true,  false><<<dim3(256, 16),       128>>>(511, nullptr, nullptr, alpha, scale, bias, out);
}